// round 10
// baseline (speedup 1.0000x reference)
#include <cuda_runtime.h>

typedef unsigned long long u64;

#define NT 512
#define GRID_BLKS 129   // 1 chain + 128 conv

// ---- chain smem (floats): slot s at s*8704 (rm 64x68, AT 64x68) ----
// sv[2][64] at 17408; scr 4096 at 17536  (total 21632)
// ---- conv smem (floats) ----
#define C_W1S 0          // 64 x 168
#define C_XS  10752      // 3 x 8 x 72
#define C_HA  12480      // 64 x 132
#define C_HB  20928      // 64 x 132
#define H0_LD 132
#define C_ADS 29376      // 64 x 128
#define C_SAS 37568      // 64
#define C_B1S 37632      // 64
#define SMEM_FLOATS 37696

__device__ float g_AD[3][8192];   // phase p: dup layout [c][2*o] of P_{8,64,128}
__device__ float g_sA[3][64];
__device__ int   g_flag[3][32];   // one 128B line per phase
__device__ int   g_done[32];

__device__ __forceinline__ u64 pk2(float a, float b) {
    u64 r; asm("mov.b64 %0, {%1, %2};" : "=l"(r) : "f"(a), "f"(b)); return r;
}
__device__ __forceinline__ float2 up2(u64 v) {
    float2 r; asm("mov.b64 {%0, %1}, %2;" : "=f"(r.x), "=f"(r.y) : "l"(v)); return r;
}
__device__ __forceinline__ void fma2(u64& d, u64 a, u64 b) {
    asm("fma.rn.f32x2 %0, %1, %2, %0;" : "+l"(d) : "l"(a), "l"(b));
}
__device__ __forceinline__ void fadd2(u64& d, u64 a) {
    asm("add.rn.f32x2 %0, %0, %1;" : "+l"(d) : "l"(a));
}

__global__ void __launch_bounds__(NT, 1)
fused(const float* __restrict__ x, const float* __restrict__ W1,
      const float* __restrict__ b1, const float* __restrict__ W2,
      const float* __restrict__ b2, float* __restrict__ out)
{
    extern __shared__ float sm[];
    const int t   = threadIdx.x;
    const int bid = blockIdx.x;

    if (bid == 0) {
        // ========== chain block: 7 squarings T1->T2->...->T128 ==========
        float* scr = sm + 17536;

        // load W2 -> slot0 (rm + AT), b2 -> sv[0]
        for (int i = t; i < 4096; i += NT) {
            int r = i >> 6, c = i & 63;
            float v = W2[i];
            sm[r * 68 + c]        = v;   // rm0
            sm[4352 + c * 68 + r] = v;   // AT0
        }
        if (t < 64) sm[17408 + t] = b2[t];
        __syncthreads();

        const int kh  = t >> 8;          // k half
        const int idx = t & 255;
        const int r0  = (idx >> 4) * 4;  // 0..60
        const int c0  = (idx & 15) * 4;  // 0..60

        int cur = 0;
#pragma unroll 1
        for (int s = 0; s < 7; ++s) {
            const int nxt = cur ^ 1;
            const float* Arm = sm + cur * 8704;
            const float* Aat = sm + cur * 8704 + 4352;
            float* Crm = sm + nxt * 8704;
            float* Cat = sm + nxt * 8704 + 4352;
            const float* svi = sm + 17408 + cur * 64;
            float* svo = sm + 17408 + nxt * 64;

            u64 acc[4][2] = {};
            {
                const float* ap = Aat + (kh * 32) * 68 + r0;
                const float* bp = Arm + (kh * 32) * 68 + c0;
#pragma unroll 8
                for (int k = 0; k < 32; ++k) {
                    float4 a = *(const float4*)ap;
                    ulonglong2 b = *(const ulonglong2*)bp;
                    u64 d0 = pk2(a.x, a.x), d1 = pk2(a.y, a.y);
                    u64 d2 = pk2(a.z, a.z), d3 = pk2(a.w, a.w);
                    fma2(acc[0][0], d0, b.x); fma2(acc[0][1], d0, b.y);
                    fma2(acc[1][0], d1, b.x); fma2(acc[1][1], d1, b.y);
                    fma2(acc[2][0], d2, b.x); fma2(acc[2][1], d2, b.y);
                    fma2(acc[3][0], d3, b.x); fma2(acc[3][1], d3, b.y);
                    ap += 68; bp += 68;
                }
            }
            if (kh == 1) {
                ulonglong2 v;
                v.x = acc[0][0]; v.y = acc[0][1]; *(ulonglong2*)(scr + idx * 16)      = v;
                v.x = acc[1][0]; v.y = acc[1][1]; *(ulonglong2*)(scr + idx * 16 + 4)  = v;
                v.x = acc[2][0]; v.y = acc[2][1]; *(ulonglong2*)(scr + idx * 16 + 8)  = v;
                v.x = acc[3][0]; v.y = acc[3][1]; *(ulonglong2*)(scr + idx * 16 + 12) = v;
            }
            __syncthreads();
            if (kh == 0) {
                ulonglong2 p0 = *(const ulonglong2*)(scr + idx * 16);
                ulonglong2 p1 = *(const ulonglong2*)(scr + idx * 16 + 4);
                ulonglong2 p2 = *(const ulonglong2*)(scr + idx * 16 + 8);
                ulonglong2 p3 = *(const ulonglong2*)(scr + idx * 16 + 12);
                fadd2(acc[0][0], p0.x); fadd2(acc[0][1], p0.y);
                fadd2(acc[1][0], p1.x); fadd2(acc[1][1], p1.y);
                fadd2(acc[2][0], p2.x); fadd2(acc[2][1], p2.y);
                fadd2(acc[3][0], p3.x); fadd2(acc[3][1], p3.y);
                ulonglong2 v;
#pragma unroll
                for (int r = 0; r < 4; ++r) {
                    v.x = acc[r][0]; v.y = acc[r][1];
                    *(ulonglong2*)(Crm + (r0 + r) * 68 + c0) = v;
                }
                float2 e0a = up2(acc[0][0]), e0b = up2(acc[0][1]);
                float2 e1a = up2(acc[1][0]), e1b = up2(acc[1][1]);
                float2 e2a = up2(acc[2][0]), e2b = up2(acc[2][1]);
                float2 e3a = up2(acc[3][0]), e3b = up2(acc[3][1]);
                *(float4*)(Cat + (c0 + 0) * 68 + r0) = make_float4(e0a.x, e1a.x, e2a.x, e3a.x);
                *(float4*)(Cat + (c0 + 1) * 68 + r0) = make_float4(e0a.y, e1a.y, e2a.y, e3a.y);
                *(float4*)(Cat + (c0 + 2) * 68 + r0) = make_float4(e0b.x, e1b.x, e2b.x, e3b.x);
                *(float4*)(Cat + (c0 + 3) * 68 + r0) = make_float4(e0b.y, e1b.y, e2b.y, e3b.y);
            } else if (t < 320) {
                // s_{2n} = P_n * s_n + s_n
                int r = t - 256;
                float ss = svi[r];
#pragma unroll 8
                for (int k = 0; k < 64; ++k)
                    ss = fmaf(Aat[k * 68 + r], svi[k], ss);
                svo[r] = ss;
            }
            __syncthreads();
            cur = nxt;

            // publish milestones: T8 (s=2), T64 (s=5), T128 (s=6)
            if (s == 2 || s == 5 || s == 6) {
                const int p = (s == 2) ? 0 : (s == 5) ? 1 : 2;
                const float* Pat = sm + cur * 8704 + 4352;
                for (int i = t; i < 4096; i += NT) {
                    int c = i >> 6, o = i & 63;
                    float v = Pat[c * 68 + o];   // = P[o][c]
                    *(float2*)(&g_AD[p][c * 128 + 2 * o]) = make_float2(v, v);
                }
                if (t < 64) g_sA[p][t] = sm[17408 + cur * 64 + t];
                __threadfence();
                __syncthreads();
                if (t == 0) atomicExch(&g_flag[p][0], 1);
            }
        }
    } else {
        // ========== conv + 3-phase apply blocks ==========
        float* W1s = sm + C_W1S;
        float* xs  = sm + C_XS;
        float* hA  = sm + C_HA;
        float* hB  = sm + C_HB;
        float* ADs = sm + C_ADS;
        float* sAs = sm + C_SAS;
        float* b1s = sm + C_B1S;

        const int r0b = (bid - 1) * 2;
        const int bb = r0b >> 6, y0 = r0b & 63;   // both rows in same image

        for (int i = t; i < 10752; i += NT) {
            int m = i / 168, jp = i % 168;
            int ii = jp / 56, r = jp % 56, ky = r / 8, kx = r % 8;
            W1s[i] = (kx < 7) ? W1[m * 147 + ii * 49 + ky * 7 + kx] : 0.0f;
        }
        if (t < 64) b1s[t] = b1[t];
        for (int i = t; i < 1728; i += NT) {
            int ii = i / 576, rem = i % 576;
            int yy = rem / 72, xx = rem % 72;
            xs[i] = (xx < 70) ? x[((bb * 3 + ii) * 70 + (y0 + yy)) * 70 + xx] : 0.0f;
        }
        __syncthreads();

        // ---- conv: hA = conv7x7(x, W1) + b1, 2 rows paired in f32x2 ----
        const int xq = t & 7, oc = t >> 3;
        const int x0 = xq * 8;

        u64 acc[8];
        {
            u64 bv = pk2(b1s[oc], b1s[oc]);
#pragma unroll
            for (int xi = 0; xi < 8; ++xi) acc[xi] = bv;
        }

#pragma unroll 1
        for (int ii = 0; ii < 3; ++ii) {
#pragma unroll 1
            for (int ky = 0; ky < 7; ++ky) {
                const float* p0 = xs + (ii * 8 + ky) * 72 + x0;
                const float* p1 = p0 + 72;
                float a0[16], a1[16];
#pragma unroll
                for (int q = 0; q < 4; ++q) {
                    float4 u = *(const float4*)(p0 + q * 4);
                    a0[q*4+0] = u.x; a0[q*4+1] = u.y; a0[q*4+2] = u.z; a0[q*4+3] = u.w;
                    float4 v = *(const float4*)(p1 + q * 4);
                    a1[q*4+0] = v.x; a1[q*4+1] = v.y; a1[q*4+2] = v.z; a1[q*4+3] = v.w;
                }
                u64 xwp[14];
#pragma unroll
                for (int i = 0; i < 14; ++i) xwp[i] = pk2(a0[i], a1[i]);

                const float* wq = W1s + oc * 168 + ii * 56 + ky * 8;
                float4 w0 = *(const float4*)(wq);
                float4 w1 = *(const float4*)(wq + 4);
                u64 wp[7];
                wp[0] = pk2(w0.x, w0.x); wp[1] = pk2(w0.y, w0.y);
                wp[2] = pk2(w0.z, w0.z); wp[3] = pk2(w0.w, w0.w);
                wp[4] = pk2(w1.x, w1.x); wp[5] = pk2(w1.y, w1.y);
                wp[6] = pk2(w1.z, w1.z);
#pragma unroll
                for (int kx = 0; kx < 7; ++kx)
#pragma unroll
                    for (int xi = 0; xi < 8; ++xi)
                        fma2(acc[xi], wp[kx], xwp[kx + xi]);
            }
        }

        {   // hA[c][px], px = row*64 + x
            float2 v[8];
#pragma unroll
            for (int xi = 0; xi < 8; ++xi) v[xi] = up2(acc[xi]);
            float* hb = hA + oc * H0_LD;
            *(float4*)(hb + x0)          = make_float4(v[0].x, v[1].x, v[2].x, v[3].x);
            *(float4*)(hb + x0 + 4)      = make_float4(v[4].x, v[5].x, v[6].x, v[7].x);
            *(float4*)(hb + 64 + x0)     = make_float4(v[0].y, v[1].y, v[2].y, v[3].y);
            *(float4*)(hb + 64 + x0 + 4) = make_float4(v[4].y, v[5].y, v[6].y, v[7].y);
        }
        __syncthreads();

        // ---- 3 affine applies: T8, then T64, then T128 ----
        const int po = t >> 4, pq = t & 15;
        const int o0 = po * 2, px0 = pq * 8;
        const int rr = px0 >> 6, xx0 = px0 & 63, yy = y0 + rr;

#pragma unroll 1
        for (int p = 0; p < 3; ++p) {
            if (t == 0) {
                while (atomicAdd(&g_flag[p][0], 0) == 0) __nanosleep(128);
            }
            __syncthreads();
            for (int i = t; i < 2048; i += NT)
                *(float4*)(ADs + 4 * i) = __ldcg((const float4*)g_AD[p] + i);
            if (t < 64) sAs[t] = __ldcg(&g_sA[p][t]);
            __syncthreads();

            const float* hin = (p & 1) ? hB : hA;
            float* hout      = (p & 1) ? hA : hB;

            u64 ap2[2][4] = {};
#pragma unroll 4
            for (int c = 0; c < 64; ++c) {
                ulonglong2 ad  = *(const ulonglong2*)(ADs + c * 128 + 4 * po);
                ulonglong2 hv0 = *(const ulonglong2*)(hin + c * H0_LD + px0);
                ulonglong2 hv1 = *(const ulonglong2*)(hin + c * H0_LD + px0 + 4);
                fma2(ap2[0][0], ad.x, hv0.x); fma2(ap2[0][1], ad.x, hv0.y);
                fma2(ap2[0][2], ad.x, hv1.x); fma2(ap2[0][3], ad.x, hv1.y);
                fma2(ap2[1][0], ad.y, hv0.x); fma2(ap2[1][1], ad.y, hv0.y);
                fma2(ap2[1][2], ad.y, hv1.x); fma2(ap2[1][3], ad.y, hv1.y);
            }

#pragma unroll
            for (int j = 0; j < 2; ++j) {
                int o = o0 + j;
                float sa = sAs[o];
                float2 v0 = up2(ap2[j][0]), v1 = up2(ap2[j][1]);
                float2 v2 = up2(ap2[j][2]), v3 = up2(ap2[j][3]);
                if (p < 2) {
                    float* pd = hout + o * H0_LD + px0;
                    *(float4*)(pd)     = make_float4(v0.x + sa, v0.y + sa, v1.x + sa, v1.y + sa);
                    *(float4*)(pd + 4) = make_float4(v2.x + sa, v2.y + sa, v3.x + sa, v3.y + sa);
                } else {
                    float* pd = out + ((bb * 64 + o) * 64 + yy) * 64 + xx0;
                    *(float4*)(pd)     = make_float4(v0.x + sa, v0.y + sa, v1.x + sa, v1.y + sa);
                    *(float4*)(pd + 4) = make_float4(v2.x + sa, v2.y + sa, v3.x + sa, v3.y + sa);
                }
            }
            __syncthreads();
        }
    }

    // ---- self-resetting counters for clean graph replays ----
    __syncthreads();
    if (t == 0) {
        __threadfence();
        int d = atomicAdd(&g_done[0], 1);
        if (d == GRID_BLKS - 1) {
            atomicExch(&g_flag[0][0], 0);
            atomicExch(&g_flag[1][0], 0);
            atomicExch(&g_flag[2][0], 0);
            atomicExch(&g_done[0], 0);
        }
    }
}

extern "C" void kernel_launch(void* const* d_in, const int* in_sizes, int n_in,
                              void* d_out, int out_size)
{
    (void)in_sizes; (void)n_in; (void)out_size;
    const float* x  = (const float*)d_in[0];
    const float* W1 = (const float*)d_in[1];
    const float* b1 = (const float*)d_in[2];
    const float* W2 = (const float*)d_in[3];
    const float* b2 = (const float*)d_in[4];
    float* out = (float*)d_out;

    const size_t smem = (size_t)SMEM_FLOATS * sizeof(float);
    cudaFuncSetAttribute(fused, cudaFuncAttributeMaxDynamicSharedMemorySize, (int)smem);
    fused<<<GRID_BLKS, NT, smem>>>(x, W1, b1, W2, b2, out);
}

// round 11
// speedup vs baseline: 1.2923x; 1.2923x over previous
#include <cuda_runtime.h>

typedef unsigned long long u64;

#define NT 512
#define GRID_BLKS 129   // 1 chain + 128 conv

// ---- chain smem (floats): slot s at s*8704 (rm 64x68 @0, MT 64x68 @4352) ----
// sv 2x64 @17408 ; scr 4096 @17536
// ---- conv smem (floats) ----
#define C_W1S 0          // 64 x 168
#define C_XS  10752      // 3 x 8 x 72
#define C_HA  12480      // 64 x 132
#define C_HB  20928      // 64 x 132
#define H0_LD 132
#define C_ADS 29376      // 64 x 128
#define C_SAS 37568      // 64
#define C_B1S 37632      // 64
#define SMEM_FLOATS 37696

__device__ float g_AD[3][8192];   // phase p: dup layout [c][2*o] of P_{8,64,128}
__device__ float g_sA[3][64];
__device__ int   g_flag[3][32];   // one 128B line per phase
__device__ int   g_done[32];

__device__ __forceinline__ u64 pk2(float a, float b) {
    u64 r; asm("mov.b64 %0, {%1, %2};" : "=l"(r) : "f"(a), "f"(b)); return r;
}
__device__ __forceinline__ float2 up2(u64 v) {
    float2 r; asm("mov.b64 {%0, %1}, %2;" : "=f"(r.x), "=f"(r.y) : "l"(v)); return r;
}
__device__ __forceinline__ void fma2(u64& d, u64 a, u64 b) {
    asm("fma.rn.f32x2 %0, %1, %2, %0;" : "+l"(d) : "l"(a), "l"(b));
}
__device__ __forceinline__ void fadd2(u64& d, u64 a) {
    asm("add.rn.f32x2 %0, %0, %1;" : "+l"(d) : "l"(a));
}

// ---------------------------------------------------------------------------
// Squaring compose (R5-proven): T_{2n} = T_n o T_n.
// Reads slot cur (rm + MT), writes slot nxt (rm + MT) and sv[nxt].
// ---------------------------------------------------------------------------
__device__ __forceinline__ void compose_sq(float* sm, int cur, int nxt, int t)
{
    const float* AT  = sm + cur * 8704 + 4352;
    const float* Brm = sm + cur * 8704;
    float* Crm = sm + nxt * 8704;
    float* CT  = sm + nxt * 8704 + 4352;
    const float* svA = sm + 17408 + cur * 64;
    float* svC = sm + 17408 + nxt * 64;
    float* scr = sm + 17536;

    const int w = t >> 5, lane = t & 31;
    const int h = w >> 3, tile = w & 7;
    const int rbase = (tile & 3) * 16, cbase = (tile >> 2) * 32;
    const int ro = lane >> 2, co = lane & 3;
    const int r0 = rbase + ro * 2, c0 = cbase + co * 8;

    u64 acc[2][4] = {};
    const float* aP = AT  + (h * 32) * 68 + r0;
    const float* bP = Brm + (h * 32) * 68 + c0;
#pragma unroll 4
    for (int kk = 0; kk < 32; ++kk) {
        float2 a = *(const float2*)aP;
        ulonglong2 b0 = *(const ulonglong2*)bP;
        ulonglong2 b1 = *(const ulonglong2*)(bP + 4);
        u64 d0 = pk2(a.x, a.x), d1 = pk2(a.y, a.y);
        fma2(acc[0][0], d0, b0.x); fma2(acc[0][1], d0, b0.y);
        fma2(acc[0][2], d0, b1.x); fma2(acc[0][3], d0, b1.y);
        fma2(acc[1][0], d1, b0.x); fma2(acc[1][1], d1, b0.y);
        fma2(acc[1][2], d1, b1.x); fma2(acc[1][3], d1, b1.y);
        aP += 68; bP += 68;
    }

    if (h == 1) {
        float* sp = scr + (tile * 32 + lane) * 4;
        ulonglong2 v;
        v.x = acc[0][0]; v.y = acc[0][1]; *(ulonglong2*)(sp)        = v;
        v.x = acc[0][2]; v.y = acc[0][3]; *(ulonglong2*)(sp + 1024) = v;
        v.x = acc[1][0]; v.y = acc[1][1]; *(ulonglong2*)(sp + 2048) = v;
        v.x = acc[1][2]; v.y = acc[1][3]; *(ulonglong2*)(sp + 3072) = v;
    }
    __syncthreads();
    if (h == 0) {
        const float* sp = scr + (tile * 32 + lane) * 4;
        ulonglong2 p0 = *(const ulonglong2*)(sp);
        ulonglong2 p1 = *(const ulonglong2*)(sp + 1024);
        ulonglong2 p2 = *(const ulonglong2*)(sp + 2048);
        ulonglong2 p3 = *(const ulonglong2*)(sp + 3072);
        fadd2(acc[0][0], p0.x); fadd2(acc[0][1], p0.y);
        fadd2(acc[0][2], p1.x); fadd2(acc[0][3], p1.y);
        fadd2(acc[1][0], p2.x); fadd2(acc[1][1], p2.y);
        fadd2(acc[1][2], p3.x); fadd2(acc[1][3], p3.y);
        ulonglong2 v;
        v.x = acc[0][0]; v.y = acc[0][1]; *(ulonglong2*)(Crm + r0 * 68 + c0)           = v;
        v.x = acc[0][2]; v.y = acc[0][3]; *(ulonglong2*)(Crm + r0 * 68 + c0 + 4)       = v;
        v.x = acc[1][0]; v.y = acc[1][1]; *(ulonglong2*)(Crm + (r0 + 1) * 68 + c0)     = v;
        v.x = acc[1][2]; v.y = acc[1][3]; *(ulonglong2*)(Crm + (r0 + 1) * 68 + c0 + 4) = v;
#pragma unroll
        for (int j = 0; j < 4; ++j) {
            float2 e0 = up2(acc[0][j]);
            float2 e1 = up2(acc[1][j]);
            float2 u;
            u.x = e0.x; u.y = e1.x; *(float2*)(CT + (c0 + 2 * j)     * 68 + r0) = u;
            u.x = e0.y; u.y = e1.y; *(float2*)(CT + (c0 + 2 * j + 1) * 68 + r0) = u;
        }
    } else if (t < 320) {
        // s_{2n} = P_n * s_n + s_n
        const int r = t - 256;
        float s = svA[r];
#pragma unroll 8
        for (int k = 0; k < 64; ++k)
            s = fmaf(AT[k * 68 + r], svA[k], s);
        svC[r] = s;
    }
    __syncthreads();
}

__global__ void __launch_bounds__(NT, 1)
fused(const float* __restrict__ x, const float* __restrict__ W1,
      const float* __restrict__ b1, const float* __restrict__ W2,
      const float* __restrict__ b2, float* __restrict__ out)
{
    extern __shared__ float sm[];
    const int t   = threadIdx.x;
    const int bid = blockIdx.x;

    if (bid == 0) {
        // ========== chain block: 7 squarings, publish T8/T64/T128 ==========
        for (int i = t; i < 4096; i += NT) {
            int r = i >> 6, c = i & 63;
            float v = W2[i];
            sm[r * 68 + c]        = v;   // slot0 rm
            sm[4352 + c * 68 + r] = v;   // slot0 MT
        }
        if (t < 64) sm[17408 + t] = b2[t];
        __syncthreads();

        int cur = 0;
#pragma unroll 1
        for (int s = 0; s < 7; ++s) {
            const int nxt = cur ^ 1;
            compose_sq(sm, cur, nxt, t);
            cur = nxt;
            if (s == 2 || s == 5 || s == 6) {
                const int p = (s == 2) ? 0 : (s == 5) ? 1 : 2;
                const float* Pat = sm + cur * 8704 + 4352;
                for (int i = t; i < 4096; i += NT) {
                    int c = i >> 6, o = i & 63;
                    float v = Pat[c * 68 + o];   // = P[o][c]
                    *(float2*)(&g_AD[p][c * 128 + 2 * o]) = make_float2(v, v);
                }
                if (t < 64) g_sA[p][t] = sm[17408 + cur * 64 + t];
                __threadfence();
                __syncthreads();
                if (t == 0) atomicExch(&g_flag[p][0], 1);
            }
        }
    } else {
        // ========== conv + 3-phase apply blocks ==========
        float* W1s = sm + C_W1S;
        float* xs  = sm + C_XS;
        float* hA  = sm + C_HA;
        float* hB  = sm + C_HB;
        float* ADs = sm + C_ADS;
        float* sAs = sm + C_SAS;
        float* b1s = sm + C_B1S;

        const int r0b = (bid - 1) * 2;
        const int bb = r0b >> 6, y0 = r0b & 63;   // both rows in same image

        for (int i = t; i < 10752; i += NT) {
            int m = i / 168, jp = i % 168;
            int ii = jp / 56, r = jp % 56, ky = r / 8, kx = r % 8;
            W1s[i] = (kx < 7) ? W1[m * 147 + ii * 49 + ky * 7 + kx] : 0.0f;
        }
        if (t < 64) b1s[t] = b1[t];
        for (int i = t; i < 1728; i += NT) {
            int ii = i / 576, rem = i % 576;
            int yy = rem / 72, xx = rem % 72;
            xs[i] = (xx < 70) ? x[((bb * 3 + ii) * 70 + (y0 + yy)) * 70 + xx] : 0.0f;
        }
        __syncthreads();

        // ---- conv: hA = conv7x7(x, W1) + b1, 2 rows paired in f32x2 ----
        const int xq = t & 7, oc = t >> 3;
        const int x0 = xq * 8;

        u64 acc[8];
        {
            u64 bv = pk2(b1s[oc], b1s[oc]);
#pragma unroll
            for (int xi = 0; xi < 8; ++xi) acc[xi] = bv;
        }

#pragma unroll 1
        for (int ii = 0; ii < 3; ++ii) {
#pragma unroll 1
            for (int ky = 0; ky < 7; ++ky) {
                const float* p0 = xs + (ii * 8 + ky) * 72 + x0;
                const float* p1 = p0 + 72;
                float a0[16], a1[16];
#pragma unroll
                for (int q = 0; q < 4; ++q) {
                    float4 u = *(const float4*)(p0 + q * 4);
                    a0[q*4+0] = u.x; a0[q*4+1] = u.y; a0[q*4+2] = u.z; a0[q*4+3] = u.w;
                    float4 v = *(const float4*)(p1 + q * 4);
                    a1[q*4+0] = v.x; a1[q*4+1] = v.y; a1[q*4+2] = v.z; a1[q*4+3] = v.w;
                }
                u64 xwp[14];
#pragma unroll
                for (int i = 0; i < 14; ++i) xwp[i] = pk2(a0[i], a1[i]);

                const float* wq = W1s + oc * 168 + ii * 56 + ky * 8;
                float4 w0 = *(const float4*)(wq);
                float4 w1 = *(const float4*)(wq + 4);
                u64 wp[7];
                wp[0] = pk2(w0.x, w0.x); wp[1] = pk2(w0.y, w0.y);
                wp[2] = pk2(w0.z, w0.z); wp[3] = pk2(w0.w, w0.w);
                wp[4] = pk2(w1.x, w1.x); wp[5] = pk2(w1.y, w1.y);
                wp[6] = pk2(w1.z, w1.z);
#pragma unroll
                for (int kx = 0; kx < 7; ++kx)
#pragma unroll
                    for (int xi = 0; xi < 8; ++xi)
                        fma2(acc[xi], wp[kx], xwp[kx + xi]);
            }
        }

        {   // hA[c][px], px = row*64 + x
            float2 v[8];
#pragma unroll
            for (int xi = 0; xi < 8; ++xi) v[xi] = up2(acc[xi]);
            float* hb = hA + oc * H0_LD;
            *(float4*)(hb + x0)          = make_float4(v[0].x, v[1].x, v[2].x, v[3].x);
            *(float4*)(hb + x0 + 4)      = make_float4(v[4].x, v[5].x, v[6].x, v[7].x);
            *(float4*)(hb + 64 + x0)     = make_float4(v[0].y, v[1].y, v[2].y, v[3].y);
            *(float4*)(hb + 64 + x0 + 4) = make_float4(v[4].y, v[5].y, v[6].y, v[7].y);
        }
        __syncthreads();

        // ---- 3 affine applies: T8, T64, T128 (exponents add) ----
        // apply tiling: 256 threads, 4 oc x 8 px each (2 B/MAC)
        const int og = (t >> 4) & 15, pq = t & 15;
        const int o0 = og * 4, px0 = pq * 8;
        const int rr = px0 >> 6, xx0 = px0 & 63, yy = y0 + rr;
        const bool act = (t < 256);

#pragma unroll 1
        for (int p = 0; p < 3; ++p) {
            if (t == 0) {
                while (atomicAdd(&g_flag[p][0], 0) == 0) __nanosleep(128);
            }
            __syncthreads();
            for (int i = t; i < 2048; i += NT)
                *(float4*)(ADs + 4 * i) = __ldcg((const float4*)g_AD[p] + i);
            if (t < 64) sAs[t] = __ldcg(&g_sA[p][t]);
            __syncthreads();

            const float* hin = (p & 1) ? hB : hA;
            float* hout      = (p & 1) ? hA : hB;

            if (act) {
                u64 ap2[4][4] = {};
#pragma unroll 4
                for (int c = 0; c < 64; ++c) {
                    const float* adp = ADs + c * 128 + 8 * og;
                    ulonglong2 ad0 = *(const ulonglong2*)(adp);
                    ulonglong2 ad1 = *(const ulonglong2*)(adp + 4);
                    ulonglong2 hv0 = *(const ulonglong2*)(hin + c * H0_LD + px0);
                    ulonglong2 hv1 = *(const ulonglong2*)(hin + c * H0_LD + px0 + 4);
                    fma2(ap2[0][0], ad0.x, hv0.x); fma2(ap2[0][1], ad0.x, hv0.y);
                    fma2(ap2[0][2], ad0.x, hv1.x); fma2(ap2[0][3], ad0.x, hv1.y);
                    fma2(ap2[1][0], ad0.y, hv0.x); fma2(ap2[1][1], ad0.y, hv0.y);
                    fma2(ap2[1][2], ad0.y, hv1.x); fma2(ap2[1][3], ad0.y, hv1.y);
                    fma2(ap2[2][0], ad1.x, hv0.x); fma2(ap2[2][1], ad1.x, hv0.y);
                    fma2(ap2[2][2], ad1.x, hv1.x); fma2(ap2[2][3], ad1.x, hv1.y);
                    fma2(ap2[3][0], ad1.y, hv0.x); fma2(ap2[3][1], ad1.y, hv0.y);
                    fma2(ap2[3][2], ad1.y, hv1.x); fma2(ap2[3][3], ad1.y, hv1.y);
                }
#pragma unroll
                for (int j = 0; j < 4; ++j) {
                    const int o = o0 + j;
                    const float sa = sAs[o];
                    float2 v0 = up2(ap2[j][0]), v1 = up2(ap2[j][1]);
                    float2 v2 = up2(ap2[j][2]), v3 = up2(ap2[j][3]);
                    if (p < 2) {
                        float* pd = hout + o * H0_LD + px0;
                        *(float4*)(pd)     = make_float4(v0.x + sa, v0.y + sa, v1.x + sa, v1.y + sa);
                        *(float4*)(pd + 4) = make_float4(v2.x + sa, v2.y + sa, v3.x + sa, v3.y + sa);
                    } else {
                        float* pd = out + ((bb * 64 + o) * 64 + yy) * 64 + xx0;
                        *(float4*)(pd)     = make_float4(v0.x + sa, v0.y + sa, v1.x + sa, v1.y + sa);
                        *(float4*)(pd + 4) = make_float4(v2.x + sa, v2.y + sa, v3.x + sa, v3.y + sa);
                    }
                }
            }
            __syncthreads();
        }
    }

    // ---- self-resetting counters for clean graph replays ----
    __syncthreads();
    if (t == 0) {
        __threadfence();
        int d = atomicAdd(&g_done[0], 1);
        if (d == GRID_BLKS - 1) {
            atomicExch(&g_flag[0][0], 0);
            atomicExch(&g_flag[1][0], 0);
            atomicExch(&g_flag[2][0], 0);
            atomicExch(&g_done[0], 0);
        }
    }
}

extern "C" void kernel_launch(void* const* d_in, const int* in_sizes, int n_in,
                              void* d_out, int out_size)
{
    (void)in_sizes; (void)n_in; (void)out_size;
    const float* x  = (const float*)d_in[0];
    const float* W1 = (const float*)d_in[1];
    const float* b1 = (const float*)d_in[2];
    const float* W2 = (const float*)d_in[3];
    const float* b2 = (const float*)d_in[4];
    float* out = (float*)d_out;

    const size_t smem = (size_t)SMEM_FLOATS * sizeof(float);
    cudaFuncSetAttribute(fused, cudaFuncAttributeMaxDynamicSharedMemorySize, (int)smem);
    fused<<<GRID_BLKS, NT, smem>>>(x, W1, b1, W2, b2, out);
}